// round 2
// baseline (speedup 1.0000x reference)
#include <cuda_runtime.h>

// GateRecurrent2dnoind: H[h,w] = B*X + G1*H[h-1,w-1] + G2*H[h,w-1] + G3*H[h+1,w-1]
// [16, 32, 128, 128] fp32. One WARP per (b,c) plane; lane l owns rows
// {l, l+32, l+64, l+96} (interleaved). Neighbor coupling via shfl only —
// zero block barriers. Inputs staged in smem (coalesced LDG, conflict-free STS),
// B*X fused at staging. Output staged in smem, flushed coalesced.

#define HH    128
#define WW    128
#define WT    32            // columns per tile
#define NT    (WW / WT)     // 4 tiles
#define PITCH 33            // smem row pitch (floats): conflict-free everywhere
#define TILE_F (HH * PITCH) // 4224 floats per staged tensor tile

#define FULL 0xFFFFFFFFu

__global__ __launch_bounds__(32)
void gaterec2d_warp_kernel(const float* __restrict__ X,
                           const float* __restrict__ Bg,
                           const float* __restrict__ G1,
                           const float* __restrict__ G2,
                           const float* __restrict__ G3,
                           float* __restrict__ O)
{
    extern __shared__ float sm[];
    float* sbx = sm;                 // B*X
    float* s1  = sm + 1 * TILE_F;    // G1
    float* s2  = sm + 2 * TILE_F;    // G2
    float* s3  = sm + 3 * TILE_F;    // G3
    float* so  = sm + 4 * TILE_F;    // output tile

    const int  l    = threadIdx.x;
    const long base = (long)blockIdx.x * (HH * WW);

    // recurrence state: H[h, w-1] for h = l, l+32, l+64, l+96
    float h0 = 0.f, h1 = 0.f, h2 = 0.f, h3 = 0.f;

    for (int tile = 0; tile < NT; ++tile) {
        const int w0 = tile * WT;

        // ---- stage: coalesced float4 loads, conflict-free scalar STS ----
        #pragma unroll 4
        for (int it = 0; it < 32; ++it) {
            const int idx = it * 32 + l;
            const int row = idx >> 3;           // 8 float4 per row
            const int c4  = (idx & 7) << 2;
            const long g  = base + (long)row * WW + w0 + c4;
            const float4 vx = *(const float4*)(X  + g);
            const float4 vb = *(const float4*)(Bg + g);
            const float4 v1 = *(const float4*)(G1 + g);
            const float4 v2 = *(const float4*)(G2 + g);
            const float4 v3 = *(const float4*)(G3 + g);
            const int s = row * PITCH + c4;
            sbx[s+0] = vb.x*vx.x; sbx[s+1] = vb.y*vx.y;
            sbx[s+2] = vb.z*vx.z; sbx[s+3] = vb.w*vx.w;
            s1[s+0] = v1.x; s1[s+1] = v1.y; s1[s+2] = v1.z; s1[s+3] = v1.w;
            s2[s+0] = v2.x; s2[s+1] = v2.y; s2[s+2] = v2.z; s2[s+3] = v2.w;
            s3[s+0] = v3.x; s3[s+1] = v3.y; s3[s+2] = v3.z; s3[s+3] = v3.w;
        }
        __syncwarp();

        // ---- scan 32 columns: shfl-only neighbor exchange, no barriers ----
        const int r0 = l * PITCH;
        #pragma unroll 4
        for (int wl = 0; wl < WT; ++wl) {
            const int sA = r0 + wl;
            const int sB = sA + 32 * PITCH;
            const int sC = sB + 32 * PITCH;
            const int sD = sC + 32 * PITCH;

            const float bx0 = sbx[sA], a10 = s1[sA], a20 = s2[sA], a30 = s3[sA];
            const float bx1 = sbx[sB], a11 = s1[sB], a21 = s2[sB], a31 = s3[sB];
            const float bx2 = sbx[sC], a12 = s1[sC], a22 = s2[sC], a32 = s3[sC];
            const float bx3 = sbx[sD], a13 = s1[sD], a23 = s2[sD], a33 = s3[sD];

            // up[k] = H_prev[row-1]: lane l-1 slot k; lane 0 needs lane 31 slot k-1.
            const float u0 = __shfl_sync(FULL, (l == 31) ? 0.f : h0, (l + 31) & 31);
            const float u1 = __shfl_sync(FULL, (l == 31) ? h0  : h1, (l + 31) & 31);
            const float u2 = __shfl_sync(FULL, (l == 31) ? h1  : h2, (l + 31) & 31);
            const float u3 = __shfl_sync(FULL, (l == 31) ? h2  : h3, (l + 31) & 31);
            // dn[k] = H_prev[row+1]: lane l+1 slot k; lane 31 needs lane 0 slot k+1.
            const float d0 = __shfl_sync(FULL, (l == 0) ? h1  : h0, (l + 1) & 31);
            const float d1 = __shfl_sync(FULL, (l == 0) ? h2  : h1, (l + 1) & 31);
            const float d2 = __shfl_sync(FULL, (l == 0) ? h3  : h2, (l + 1) & 31);
            const float d3 = __shfl_sync(FULL, (l == 0) ? 0.f : h3, (l + 1) & 31);

            const float n0 = fmaf(a10, u0, fmaf(a20, h0, fmaf(a30, d0, bx0)));
            const float n1 = fmaf(a11, u1, fmaf(a21, h1, fmaf(a31, d1, bx1)));
            const float n2 = fmaf(a12, u2, fmaf(a22, h2, fmaf(a32, d2, bx2)));
            const float n3 = fmaf(a13, u3, fmaf(a23, h3, fmaf(a33, d3, bx3)));

            h0 = n0; h1 = n1; h2 = n2; h3 = n3;
            so[sA] = n0; so[sB] = n1; so[sC] = n2; so[sD] = n3;
        }
        __syncwarp();

        // ---- flush: conflict-free scalar LDS, coalesced float4 STG ----
        #pragma unroll 4
        for (int it = 0; it < 32; ++it) {
            const int idx = it * 32 + l;
            const int row = idx >> 3;
            const int c4  = (idx & 7) << 2;
            const int s   = row * PITCH + c4;
            float4 v;
            v.x = so[s+0]; v.y = so[s+1]; v.z = so[s+2]; v.w = so[s+3];
            *(float4*)(O + base + (long)row * WW + w0 + c4) = v;
        }
        __syncwarp();
    }
}

extern "C" void kernel_launch(void* const* d_in, const int* in_sizes, int n_in,
                              void* d_out, int out_size)
{
    const float* X  = (const float*)d_in[0];
    const float* B  = (const float*)d_in[1];
    const float* G1 = (const float*)d_in[2];
    const float* G2 = (const float*)d_in[3];
    const float* G3 = (const float*)d_in[4];
    float* O = (float*)d_out;

    const int planes = 16 * 32;  // 512 warps, one per plane
    const int smem_bytes = 5 * TILE_F * sizeof(float);  // ~84.5 KB

    cudaFuncSetAttribute(gaterec2d_warp_kernel,
                         cudaFuncAttributeMaxDynamicSharedMemorySize, smem_bytes);

    gaterec2d_warp_kernel<<<planes, 32, smem_bytes>>>(X, B, G1, G2, G3, O);
}

// round 3
// speedup vs baseline: 4.9021x; 4.9021x over previous
#include <cuda_runtime.h>

// GateRecurrent2dnoind: H[h,w] = B*X + G1*H[h-1,w-1] + G2*H[h,w-1] + G3*H[h+1,w-1]
// [16, 32, 128, 128] fp32.
// CTA = 128 threads = 4 warps; warp k privately owns plane blockIdx.x*4+k.
// Lane l owns rows {l, l+32, l+64, l+96}; h±1 coupling via __shfl only.
// Zero block barriers. Warp-private smem tiles: coalesced LDG/STG, conflict-free LDS.

#define HH     128
#define WW     128
#define WT     16               // columns per tile
#define NT     (WW / WT)        // 8 tiles
#define PITCH  17               // smem row pitch (floats), gcd(17,32)=1 -> conflict-free
#define TILE_F (HH * PITCH)     // 2176 floats per tensor tile
#define WSLOT  (5 * TILE_F)     // bx, g1, g2, g3, out per warp

#define FULL 0xFFFFFFFFu

__global__ __launch_bounds__(128)
void gaterec2d_wp_kernel(const float* __restrict__ X,
                         const float* __restrict__ Bg,
                         const float* __restrict__ G1,
                         const float* __restrict__ G2,
                         const float* __restrict__ G3,
                         float* __restrict__ O)
{
    extern __shared__ float sm[];

    const int wid = threadIdx.x >> 5;
    const int l   = threadIdx.x & 31;

    float* sbx = sm + wid * WSLOT;        // B*X (fused)
    float* s1  = sbx + TILE_F;            // G1
    float* s2  = s1  + TILE_F;            // G2
    float* s3  = s2  + TILE_F;            // G3
    float* so  = s3  + TILE_F;            // output tile

    const long base = ((long)blockIdx.x * 4 + wid) * (HH * WW);

    // recurrence state: H[h, w-1] for h = l, l+32, l+64, l+96
    float h0 = 0.f, h1 = 0.f, h2 = 0.f, h3 = 0.f;

    for (int tile = 0; tile < NT; ++tile) {
        const int w0 = tile * WT;

        // ---- stage: coalesced LDG.128, fuse B*X, store to warp-private tiles ----
        // 128 rows x 16 cols = 512 float4; 16 per lane.
        #pragma unroll
        for (int it = 0; it < 16; ++it) {
            const int idx = it * 32 + l;
            const int row = idx >> 2;            // 4 float4 per row
            const int c4  = (idx & 3) << 2;
            const long g  = base + (long)row * WW + w0 + c4;
            const float4 vx = *(const float4*)(X  + g);
            const float4 vb = *(const float4*)(Bg + g);
            const float4 v1 = *(const float4*)(G1 + g);
            const float4 v2 = *(const float4*)(G2 + g);
            const float4 v3 = *(const float4*)(G3 + g);
            const int s = row * PITCH + c4;
            sbx[s+0] = vb.x*vx.x; sbx[s+1] = vb.y*vx.y;
            sbx[s+2] = vb.z*vx.z; sbx[s+3] = vb.w*vx.w;
            s1[s+0] = v1.x; s1[s+1] = v1.y; s1[s+2] = v1.z; s1[s+3] = v1.w;
            s2[s+0] = v2.x; s2[s+1] = v2.y; s2[s+2] = v2.z; s2[s+3] = v2.w;
            s3[s+0] = v3.x; s3[s+1] = v3.y; s3[s+2] = v3.z; s3[s+3] = v3.w;
        }
        __syncwarp();

        // ---- scan WT columns: shfl-only neighbor exchange ----
        const int r0 = l * PITCH;
        #pragma unroll
        for (int wl = 0; wl < WT; ++wl) {
            const int sA = r0 + wl;
            const int sB = sA + 32 * PITCH;
            const int sC = sB + 32 * PITCH;
            const int sD = sC + 32 * PITCH;

            const float bx0 = sbx[sA], a10 = s1[sA], a20 = s2[sA], a30 = s3[sA];
            const float bx1 = sbx[sB], a11 = s1[sB], a21 = s2[sB], a31 = s3[sB];
            const float bx2 = sbx[sC], a12 = s1[sC], a22 = s2[sC], a32 = s3[sC];
            const float bx3 = sbx[sD], a13 = s1[sD], a23 = s2[sD], a33 = s3[sD];

            // up = H_prev[row-1]: from lane l-1 slot k; lane 0 needs lane 31 slot k-1.
            const float u0 = __shfl_sync(FULL, (l == 31) ? 0.f : h0, (l + 31) & 31);
            const float u1 = __shfl_sync(FULL, (l == 31) ? h0  : h1, (l + 31) & 31);
            const float u2 = __shfl_sync(FULL, (l == 31) ? h1  : h2, (l + 31) & 31);
            const float u3 = __shfl_sync(FULL, (l == 31) ? h2  : h3, (l + 31) & 31);
            // dn = H_prev[row+1]: from lane l+1 slot k; lane 31 needs lane 0 slot k+1.
            const float d0 = __shfl_sync(FULL, (l == 0) ? h1  : h0, (l + 1) & 31);
            const float d1 = __shfl_sync(FULL, (l == 0) ? h2  : h1, (l + 1) & 31);
            const float d2 = __shfl_sync(FULL, (l == 0) ? h3  : h2, (l + 1) & 31);
            const float d3 = __shfl_sync(FULL, (l == 0) ? 0.f : h3, (l + 1) & 31);

            h0 = fmaf(a10, u0, fmaf(a20, h0, fmaf(a30, d0, bx0)));
            h1 = fmaf(a11, u1, fmaf(a21, h1, fmaf(a31, d1, bx1)));
            h2 = fmaf(a12, u2, fmaf(a22, h2, fmaf(a32, d2, bx2)));
            h3 = fmaf(a13, u3, fmaf(a23, h3, fmaf(a33, d3, bx3)));

            so[sA] = h0; so[sB] = h1; so[sC] = h2; so[sD] = h3;
        }
        __syncwarp();

        // ---- flush: scalar LDS gather (near conflict-free), coalesced STG.128 ----
        #pragma unroll
        for (int it = 0; it < 16; ++it) {
            const int idx = it * 32 + l;
            const int row = idx >> 2;
            const int c4  = (idx & 3) << 2;
            const int s   = row * PITCH + c4;
            float4 v;
            v.x = so[s+0]; v.y = so[s+1]; v.z = so[s+2]; v.w = so[s+3];
            *(float4*)(O + base + (long)row * WW + w0 + c4) = v;
        }
        __syncwarp();
    }
}

extern "C" void kernel_launch(void* const* d_in, const int* in_sizes, int n_in,
                              void* d_out, int out_size)
{
    const float* X  = (const float*)d_in[0];
    const float* B  = (const float*)d_in[1];
    const float* G1 = (const float*)d_in[2];
    const float* G2 = (const float*)d_in[3];
    const float* G3 = (const float*)d_in[4];
    float* O = (float*)d_out;

    const int blocks = (16 * 32) / 4;                    // 128 CTAs, 4 planes each
    const int smem_bytes = 4 * WSLOT * sizeof(float);    // 174,080 B

    cudaFuncSetAttribute(gaterec2d_wp_kernel,
                         cudaFuncAttributeMaxDynamicSharedMemorySize, smem_bytes);

    gaterec2d_wp_kernel<<<blocks, 128, smem_bytes>>>(X, B, G1, G2, G3, O);
}

// round 4
// speedup vs baseline: 5.0590x; 1.0320x over previous
#include <cuda_runtime.h>
#include <cstdint>

// GateRecurrent2dnoind: H[h,w] = B*X + G1*H[h-1,w-1] + G2*H[h,w-1] + G3*H[h+1,w-1]
// [16, 32, 128, 128] fp32.
// CTA = 64 threads = 2 warps; warp k owns plane blockIdx.x*2+k (grid 256).
// Lane l owns rows {l, l+32, l+64, l+96}; h±1 coupling via __shfl only.
// cp.async double-buffered tile pipeline (WT=8 columns): prefetch tile t+1
// while scanning tile t. Flat smem tiles with XOR-swizzled float4 groups.

#define HH 128
#define WW 128
#define WT 8
#define NT (WW / WT)          // 16 tiles
#define TILE_F (HH * WT)      // 1024 floats = 4KB per tensor tile
#define WARP_TILES 11         // 2 bufs x 5 tensors + 1 out
#define WSLOT (WARP_TILES * TILE_F)

#define FULL 0xFFFFFFFFu

// float4 component by (unrolled) constant index
#define COMP(v, j) ((j) == 0 ? (v).x : (j) == 1 ? (v).y : (j) == 2 ? (v).z : (v).w)

__device__ __forceinline__ void cpa16(uint32_t dst, const float* src) {
    asm volatile("cp.async.cg.shared.global [%0], [%1], 16;\n" :: "r"(dst), "l"(src));
}
__device__ __forceinline__ void cpa_commit() {
    asm volatile("cp.async.commit_group;\n" ::: "memory");
}
__device__ __forceinline__ void cpa_wait1() {
    asm volatile("cp.async.wait_group 1;\n" ::: "memory");
}
__device__ __forceinline__ void cpa_wait0() {
    asm volatile("cp.async.wait_group 0;\n" ::: "memory");
}

__global__ __launch_bounds__(64)
void gaterec2d_pipe_kernel(const float* __restrict__ X,
                           const float* __restrict__ Bg,
                           const float* __restrict__ G1,
                           const float* __restrict__ G2,
                           const float* __restrict__ G3,
                           float* __restrict__ O)
{
    extern __shared__ float sm[];

    const int wid = threadIdx.x >> 5;
    const int l   = threadIdx.x & 31;

    float*   wbase   = sm + wid * WSLOT;
    const uint32_t wbase_u = (uint32_t)__cvta_generic_to_shared(wbase);
    float*   sout    = wbase + 10 * TILE_F;

    const long base = ((long)blockIdx.x * 2 + wid) * (HH * WW);
    const float* pX  = X  + base;
    const float* pB  = Bg + base;
    const float* p1  = G1 + base;
    const float* p2  = G2 + base;
    const float* p3  = G3 + base;
    float*       pO  = O  + base;

    // ---- stage tile `t` into buffer `buf` via cp.async (one commit group) ----
    // per lane: 8 iterations x 5 tensors = 40 cp.async.16B
    auto stage = [&](int t, int buf) {
        const int w0 = t * WT;
        const uint32_t bbase = wbase_u + (uint32_t)(buf * 5 * TILE_F) * 4u;
        #pragma unroll
        for (int it = 0; it < 8; ++it) {
            const int idx = it * 32 + l;            // 0..255 float4 slots
            const int row = idx >> 1;               // 2 groups per row
            const int g   = idx & 1;
            const int gs  = g ^ (row & 1);          // XOR swizzle
            const uint32_t doff = bbase + (uint32_t)(row * WT + 4 * gs) * 4u;
            const long     goff = (long)row * WW + w0 + 4 * g;
            cpa16(doff + 0u * TILE_F * 4u, pX + goff);
            cpa16(doff + 1u * TILE_F * 4u, pB + goff);
            cpa16(doff + 2u * TILE_F * 4u, p1 + goff);
            cpa16(doff + 3u * TILE_F * 4u, p2 + goff);
            cpa16(doff + 4u * TILE_F * 4u, p3 + goff);
        }
        cpa_commit();
    };

    // prologue: prefetch tile 0
    stage(0, 0);

    // recurrence state: H[h, w-1] for h = l, l+32, l+64, l+96
    float h0 = 0.f, h1 = 0.f, h2 = 0.f, h3 = 0.f;

    const int gsv = 0 ^ (l & 1);  // swizzled group for slot rows (row&1 == l&1)

    #pragma unroll 1
    for (int t = 0; t < NT; ++t) {
        const int buf = t & 1;

        if (t + 1 < NT) { stage(t + 1, buf ^ 1); cpa_wait1(); }
        else            { cpa_wait0(); }
        __syncwarp();

        float* bx = wbase + buf * 5 * TILE_F;  // X
        float* bb = bx + TILE_F;               // B
        float* b1 = bb + TILE_F;               // G1
        float* b2 = b1 + TILE_F;               // G2
        float* b3 = b2 + TILE_F;               // G3

        // ---- scan 8 columns in two 4-column groups ----
        #pragma unroll
        for (int g = 0; g < 2; ++g) {
            const int gsw = g ^ (l & 1);
            float4 xv[4], bv[4], a1[4], a2[4], a3[4];
            #pragma unroll
            for (int k = 0; k < 4; ++k) {
                const int off = (l + 32 * k) * WT + 4 * gsw;
                xv[k] = *(const float4*)(bx + off);
                bv[k] = *(const float4*)(bb + off);
                a1[k] = *(const float4*)(b1 + off);
                a2[k] = *(const float4*)(b2 + off);
                a3[k] = *(const float4*)(b3 + off);
            }

            float ov[4][4];
            #pragma unroll
            for (int j = 0; j < 4; ++j) {
                const float bx0 = COMP(bv[0], j) * COMP(xv[0], j);
                const float bx1 = COMP(bv[1], j) * COMP(xv[1], j);
                const float bx2 = COMP(bv[2], j) * COMP(xv[2], j);
                const float bx3 = COMP(bv[3], j) * COMP(xv[3], j);

                // up = H_prev[row-1]: lane l-1 slot k; lane 0 needs lane 31 slot k-1
                const float u0 = __shfl_sync(FULL, (l == 31) ? 0.f : h0, (l + 31) & 31);
                const float u1 = __shfl_sync(FULL, (l == 31) ? h0  : h1, (l + 31) & 31);
                const float u2 = __shfl_sync(FULL, (l == 31) ? h1  : h2, (l + 31) & 31);
                const float u3 = __shfl_sync(FULL, (l == 31) ? h2  : h3, (l + 31) & 31);
                // dn = H_prev[row+1]: lane l+1 slot k; lane 31 needs lane 0 slot k+1
                const float d0 = __shfl_sync(FULL, (l == 0) ? h1  : h0, (l + 1) & 31);
                const float d1 = __shfl_sync(FULL, (l == 0) ? h2  : h1, (l + 1) & 31);
                const float d2 = __shfl_sync(FULL, (l == 0) ? h3  : h2, (l + 1) & 31);
                const float d3 = __shfl_sync(FULL, (l == 0) ? 0.f : h3, (l + 1) & 31);

                h0 = fmaf(COMP(a1[0], j), u0, fmaf(COMP(a2[0], j), h0, fmaf(COMP(a3[0], j), d0, bx0)));
                h1 = fmaf(COMP(a1[1], j), u1, fmaf(COMP(a2[1], j), h1, fmaf(COMP(a3[1], j), d1, bx1)));
                h2 = fmaf(COMP(a1[2], j), u2, fmaf(COMP(a2[2], j), h2, fmaf(COMP(a3[2], j), d2, bx2)));
                h3 = fmaf(COMP(a1[3], j), u3, fmaf(COMP(a2[3], j), h3, fmaf(COMP(a3[3], j), d3, bx3)));

                ov[0][j] = h0; ov[1][j] = h1; ov[2][j] = h2; ov[3][j] = h3;
            }

            #pragma unroll
            for (int k = 0; k < 4; ++k) {
                float4 v;
                v.x = ov[k][0]; v.y = ov[k][1]; v.z = ov[k][2]; v.w = ov[k][3];
                *(float4*)(sout + (l + 32 * k) * WT + 4 * gsw) = v;
            }
        }
        __syncwarp();

        // ---- flush output tile: LDS.128 + coalesced STG.128 ----
        const int w0 = t * WT;
        #pragma unroll
        for (int it = 0; it < 8; ++it) {
            const int idx = it * 32 + l;
            const int row = idx >> 1;
            const int g   = idx & 1;
            const int gs  = g ^ (row & 1);
            const float4 v = *(const float4*)(sout + row * WT + 4 * gs);
            *(float4*)(pO + (long)row * WW + w0 + 4 * g) = v;
        }
        __syncwarp();
    }
    (void)gsv;
}

extern "C" void kernel_launch(void* const* d_in, const int* in_sizes, int n_in,
                              void* d_out, int out_size)
{
    const float* X  = (const float*)d_in[0];
    const float* B  = (const float*)d_in[1];
    const float* G1 = (const float*)d_in[2];
    const float* G2 = (const float*)d_in[3];
    const float* G3 = (const float*)d_in[4];
    float* O = (float*)d_out;

    const int blocks = (16 * 32) / 2;                      // 256 CTAs, 2 planes each
    const int smem_bytes = 2 * WSLOT * sizeof(float);      // 90,112 B

    cudaFuncSetAttribute(gaterec2d_pipe_kernel,
                         cudaFuncAttributeMaxDynamicSharedMemorySize, smem_bytes);

    gaterec2d_pipe_kernel<<<blocks, 64, smem_bytes>>>(X, B, G1, G2, G3, O);
}

// round 5
// speedup vs baseline: 5.2264x; 1.0331x over previous
#include <cuda_runtime.h>
#include <cstdint>

// GateRecurrent2dnoind: H[h,w] = B*X + G1*H[h-1,w-1] + G2*H[h,w-1] + G3*H[h+1,w-1]
// [16, 32, 128, 128] fp32.
// CTA = 64 threads = 2 warps; warp k owns plane blockIdx.x*2+k (grid 256).
// Lane l owns rows {l, l+32, l+64, l+96}; h±1 coupling via __shfl only.
// cp.async double-buffered 8-column subtile pipeline with .L2::128B promotion
// (each 16B fetch pulls the full 128B line into L2 -> later subtiles hit L2).
// Output accumulated in a 32-column buffer, flushed as full 128B lines.

#define HH 128
#define WW 128
#define WT 8
#define NT (WW / WT)            // 16 subtiles
#define TILE_F (HH * WT)        // 1024 floats per tensor subtile
#define OUT_F  (HH * 32)        // 4096 floats: 32-column output batch
#define WSLOT (10 * TILE_F + OUT_F)   // 2 bufs x 5 tensors + out = 14336 floats

#define FULL 0xFFFFFFFFu
#define COMP(v, j) ((j) == 0 ? (v).x : (j) == 1 ? (v).y : (j) == 2 ? (v).z : (v).w)

__device__ __forceinline__ void cpa16(uint32_t dst, const float* src) {
    asm volatile("cp.async.cg.shared.global.L2::128B [%0], [%1], 16;\n"
                 :: "r"(dst), "l"(src));
}
__device__ __forceinline__ void cpa_commit() {
    asm volatile("cp.async.commit_group;\n" ::: "memory");
}
__device__ __forceinline__ void cpa_wait1() {
    asm volatile("cp.async.wait_group 1;\n" ::: "memory");
}
__device__ __forceinline__ void cpa_wait0() {
    asm volatile("cp.async.wait_group 0;\n" ::: "memory");
}

__global__ __launch_bounds__(64)
void gaterec2d_l2p_kernel(const float* __restrict__ X,
                          const float* __restrict__ Bg,
                          const float* __restrict__ G1,
                          const float* __restrict__ G2,
                          const float* __restrict__ G3,
                          float* __restrict__ O)
{
    extern __shared__ float sm[];

    const int wid = threadIdx.x >> 5;
    const int l   = threadIdx.x & 31;

    float* wbase = sm + wid * WSLOT;
    const uint32_t wbase_u = (uint32_t)__cvta_generic_to_shared(wbase);
    float* sout  = wbase + 10 * TILE_F;   // 128 rows x 32 cols, XOR-swizzled

    const long base = ((long)blockIdx.x * 2 + wid) * (HH * WW);
    const float* pX = X  + base;
    const float* pB = Bg + base;
    const float* p1 = G1 + base;
    const float* p2 = G2 + base;
    const float* p3 = G3 + base;
    float*       pO = O  + base;

    // ---- stage subtile t (8 cols) into buffer buf; one commit group ----
    auto stage = [&](int t, int buf) {
        const int w0 = t * WT;
        const uint32_t bbase = wbase_u + (uint32_t)(buf * 5 * TILE_F) * 4u;
        #pragma unroll
        for (int it = 0; it < 8; ++it) {
            const int idx = it * 32 + l;           // 256 float4 slots
            const int row = idx >> 1;
            const int g   = idx & 1;
            const int gs  = g ^ (row & 1);         // input-tile swizzle
            const uint32_t doff = bbase + (uint32_t)(row * WT + 4 * gs) * 4u;
            const long     goff = (long)row * WW + w0 + 4 * g;
            cpa16(doff + 0u * TILE_F * 4u, pX + goff);
            cpa16(doff + 1u * TILE_F * 4u, pB + goff);
            cpa16(doff + 2u * TILE_F * 4u, p1 + goff);
            cpa16(doff + 3u * TILE_F * 4u, p2 + goff);
            cpa16(doff + 4u * TILE_F * 4u, p3 + goff);
        }
        cpa_commit();
    };

    stage(0, 0);   // prologue

    // recurrence state: H[h, w-1] for h = l, l+32, l+64, l+96
    float h0 = 0.f, h1 = 0.f, h2 = 0.f, h3 = 0.f;

    #pragma unroll 1
    for (int t = 0; t < NT; ++t) {
        const int buf = t & 1;

        if (t + 1 < NT) { stage(t + 1, buf ^ 1); cpa_wait1(); }
        else            { cpa_wait0(); }
        __syncwarp();

        float* bx = wbase + buf * 5 * TILE_F;
        float* bb = bx + TILE_F;
        float* b1 = bb + TILE_F;
        float* b2 = b1 + TILE_F;
        float* b3 = b2 + TILE_F;

        // ---- scan 8 columns as two 4-column groups ----
        #pragma unroll
        for (int g = 0; g < 2; ++g) {
            const int gsw = g ^ (l & 1);           // row&1 == l&1 for owned rows
            float4 xv[4], bv[4], a1[4], a2[4], a3[4];
            #pragma unroll
            for (int k = 0; k < 4; ++k) {
                const int off = (l + 32 * k) * WT + 4 * gsw;
                xv[k] = *(const float4*)(bx + off);
                bv[k] = *(const float4*)(bb + off);
                a1[k] = *(const float4*)(b1 + off);
                a2[k] = *(const float4*)(b2 + off);
                a3[k] = *(const float4*)(b3 + off);
            }

            float ov[4][4];
            #pragma unroll
            for (int j = 0; j < 4; ++j) {
                const float bx0 = COMP(bv[0], j) * COMP(xv[0], j);
                const float bx1 = COMP(bv[1], j) * COMP(xv[1], j);
                const float bx2 = COMP(bv[2], j) * COMP(xv[2], j);
                const float bx3 = COMP(bv[3], j) * COMP(xv[3], j);

                const float u0 = __shfl_sync(FULL, (l == 31) ? 0.f : h0, (l + 31) & 31);
                const float u1 = __shfl_sync(FULL, (l == 31) ? h0  : h1, (l + 31) & 31);
                const float u2 = __shfl_sync(FULL, (l == 31) ? h1  : h2, (l + 31) & 31);
                const float u3 = __shfl_sync(FULL, (l == 31) ? h2  : h3, (l + 31) & 31);
                const float d0 = __shfl_sync(FULL, (l == 0) ? h1  : h0, (l + 1) & 31);
                const float d1 = __shfl_sync(FULL, (l == 0) ? h2  : h1, (l + 1) & 31);
                const float d2 = __shfl_sync(FULL, (l == 0) ? h3  : h2, (l + 1) & 31);
                const float d3 = __shfl_sync(FULL, (l == 0) ? 0.f : h3, (l + 1) & 31);

                h0 = fmaf(COMP(a1[0], j), u0, fmaf(COMP(a2[0], j), h0, fmaf(COMP(a3[0], j), d0, bx0)));
                h1 = fmaf(COMP(a1[1], j), u1, fmaf(COMP(a2[1], j), h1, fmaf(COMP(a3[1], j), d1, bx1)));
                h2 = fmaf(COMP(a1[2], j), u2, fmaf(COMP(a2[2], j), h2, fmaf(COMP(a3[2], j), d2, bx2)));
                h3 = fmaf(COMP(a1[3], j), u3, fmaf(COMP(a2[3], j), h3, fmaf(COMP(a3[3], j), d3, bx3)));

                ov[0][j] = h0; ov[1][j] = h1; ov[2][j] = h2; ov[3][j] = h3;
            }

            // store into 32-col output buffer, swizzle (G+row)&7 on 16B groups
            const int G = (t & 3) * 2 + g;   // global float4-group within 32 cols
            #pragma unroll
            for (int k = 0; k < 4; ++k) {
                const int row = l + 32 * k;
                const int sg  = (G + row) & 7;
                float4 v;
                v.x = ov[k][0]; v.y = ov[k][1]; v.z = ov[k][2]; v.w = ov[k][3];
                *(float4*)(sout + row * 32 + 4 * sg) = v;
            }
        }
        __syncwarp();

        // ---- every 4 subtiles: flush 32 contiguous columns as full 128B lines ----
        if ((t & 3) == 3) {
            const int w0s = (t >> 2) * 32;
            #pragma unroll
            for (int it = 0; it < 32; ++it) {
                const int idx = it * 32 + l;       // 1024 float4 slots
                const int row = idx >> 3;          // 8 groups per row
                const int G   = idx & 7;
                const int sg  = (G + row) & 7;
                const float4 v = *(const float4*)(sout + row * 32 + 4 * sg);
                *(float4*)(pO + (long)row * WW + w0s + 4 * G) = v;
            }
            __syncwarp();
        }
    }
}

extern "C" void kernel_launch(void* const* d_in, const int* in_sizes, int n_in,
                              void* d_out, int out_size)
{
    const float* X  = (const float*)d_in[0];
    const float* B  = (const float*)d_in[1];
    const float* G1 = (const float*)d_in[2];
    const float* G2 = (const float*)d_in[3];
    const float* G3 = (const float*)d_in[4];
    float* O = (float*)d_out;

    const int blocks = (16 * 32) / 2;                    // 256 CTAs, 2 planes each
    const int smem_bytes = 2 * WSLOT * sizeof(float);    // 114,688 B

    cudaFuncSetAttribute(gaterec2d_l2p_kernel,
                         cudaFuncAttributeMaxDynamicSharedMemorySize, smem_bytes);

    gaterec2d_l2p_kernel<<<blocks, 64, smem_bytes>>>(X, B, G1, G2, G3, O);
}

// round 6
// speedup vs baseline: 7.8456x; 1.5012x over previous
#include <cuda_runtime.h>
#include <cuda.h>
#include <dlfcn.h>
#include <cstdint>

// GateRecurrent2dnoind: H[h,w] = B*X + G1*H[h-1,w-1] + G2*H[h,w-1] + G3*H[h+1,w-1]
// [16, 32, 128, 128] fp32.
// 1 CTA = 1 plane, 64 threads. Thread 0: TMA producer (depth-4 mbarrier ring,
// 8-col stages of 5 tensors). Warp 1: consumer shfl scan (lane l owns rows
// l, l+32, l+64, l+96), output accumulated in SW128-swizzled 32-col smem batch,
// flushed via TMA store. All bulk traffic bypasses the L1tex fill path.

#define HH      128
#define WT      8
#define NT      16
#define DEPTH   4
#define SLOT_F  (HH * WT)          // 1024 floats / tensor / stage
#define STAGE_F (5 * SLOT_F)       // 5120 floats = 20KB / stage
#define IN_F    (DEPTH * STAGE_F)  // 20480 floats
#define SOUT_F  (HH * 32)          // 4096 floats = 16KB
#define SM_F    (IN_F + SOUT_F)
#define BAR_OFF (SM_F * 4)         // byte offset of mbarriers
#define SMEM_BYTES (BAR_OFF + 128)
#define STAGE_BYTES (STAGE_F * 4)  // 20480

#define FULLM 0xFFFFFFFFu
#define COMP(v, j) ((j) == 0 ? (v).x : (j) == 1 ? (v).y : (j) == 2 ? (v).z : (v).w)

// ---------------- PTX helpers ----------------
__device__ __forceinline__ void mbar_init(uint32_t a, uint32_t cnt) {
    asm volatile("mbarrier.init.shared.b64 [%0], %1;" :: "r"(a), "r"(cnt) : "memory");
}
__device__ __forceinline__ void mbar_expect_tx(uint32_t a, uint32_t bytes) {
    asm volatile("mbarrier.arrive.expect_tx.shared.b64 _, [%0], %1;"
                 :: "r"(a), "r"(bytes) : "memory");
}
__device__ __forceinline__ void mbar_arrive(uint32_t a) {
    asm volatile("mbarrier.arrive.shared.b64 _, [%0];" :: "r"(a) : "memory");
}
__device__ __forceinline__ void mbar_wait_acq(uint32_t a, uint32_t ph) {
    asm volatile(
        "{\n\t.reg .pred P;\n"
        "W%=:\n\t"
        "mbarrier.try_wait.parity.acquire.cta.shared::cta.b64 P, [%0], %1, 0x989680;\n\t"
        "@P bra D%=;\n\t"
        "bra W%=;\n"
        "D%=:\n\t}"
        :: "r"(a), "r"(ph) : "memory");
}
__device__ __forceinline__ void mbar_wait_rlx(uint32_t a, uint32_t ph) {
    asm volatile(
        "{\n\t.reg .pred P;\n"
        "W%=:\n\t"
        "mbarrier.try_wait.parity.relaxed.cta.shared::cta.b64 P, [%0], %1, 0x989680;\n\t"
        "@P bra D%=;\n\t"
        "bra W%=;\n"
        "D%=:\n\t}"
        :: "r"(a), "r"(ph) : "memory");
}
__device__ __forceinline__ void tma_ld2d(uint32_t smem, const void* map,
                                         int32_t cx, int32_t cy, uint32_t mbar) {
    asm volatile(
        "cp.async.bulk.tensor.2d.shared::cta.global.tile.mbarrier::complete_tx::bytes "
        "[%0], [%1, {%2, %3}], [%4];"
        :: "r"(smem), "l"(map), "r"(cx), "r"(cy), "r"(mbar) : "memory");
}
__device__ __forceinline__ void tma_st2d(const void* map, int32_t cx, int32_t cy,
                                         uint32_t smem) {
    asm volatile(
        "cp.async.bulk.tensor.2d.global.shared::cta.tile.bulk_group "
        "[%0, {%1, %2}], [%3];"
        :: "l"(map), "r"(cx), "r"(cy), "r"(smem) : "memory");
}
__device__ __forceinline__ void tma_st_commit() {
    asm volatile("cp.async.bulk.commit_group;" ::: "memory");
}
__device__ __forceinline__ void tma_st_wait0() {
    asm volatile("cp.async.bulk.wait_group 0;" ::: "memory");
}
__device__ __forceinline__ void fence_async_shared() {
    asm volatile("fence.proxy.async.shared::cta;" ::: "memory");
}

// ---------------- kernel ----------------
__global__ __launch_bounds__(64)
void gaterec2d_tma_kernel(const __grid_constant__ CUtensorMap mX,
                          const __grid_constant__ CUtensorMap mB,
                          const __grid_constant__ CUtensorMap m1,
                          const __grid_constant__ CUtensorMap m2,
                          const __grid_constant__ CUtensorMap m3,
                          const __grid_constant__ CUtensorMap mO)
{
    extern __shared__ float smf[];
    const uint32_t sb = (uint32_t)__cvta_generic_to_shared(smf);
    const int tid = threadIdx.x;
    const int cy  = blockIdx.x * HH;   // y coordinate of this plane

    const uint32_t fullb  = sb + BAR_OFF;        // full[s]  at +8*s
    const uint32_t emptyb = sb + BAR_OFF + 32;   // empty[s] at +8*s

    if (tid == 0) {
        #pragma unroll
        for (int s = 0; s < DEPTH; ++s) {
            mbar_init(fullb  + 8u * s, 1);
            mbar_init(emptyb + 8u * s, 1);
        }
    }
    __syncthreads();

    if (tid == 0) {
        // ---------------- producer ----------------
        #pragma unroll 1
        for (int t = 0; t < NT; ++t) {
            const int s = t & 3, k = t >> 2;
            mbar_wait_rlx(emptyb + 8u * s, (uint32_t)((k & 1) ^ 1));
            mbar_expect_tx(fullb + 8u * s, STAGE_BYTES);
            const uint32_t slot = sb + (uint32_t)(s * STAGE_F) * 4u;
            const int cx = WT * t;
            tma_ld2d(slot + 0u * SLOT_F * 4u, &mX, cx, cy, fullb + 8u * s);
            tma_ld2d(slot + 1u * SLOT_F * 4u, &mB, cx, cy, fullb + 8u * s);
            tma_ld2d(slot + 2u * SLOT_F * 4u, &m1, cx, cy, fullb + 8u * s);
            tma_ld2d(slot + 3u * SLOT_F * 4u, &m2, cx, cy, fullb + 8u * s);
            tma_ld2d(slot + 4u * SLOT_F * 4u, &m3, cx, cy, fullb + 8u * s);
        }
    } else if (tid >= 32) {
        // ---------------- consumer (warp 1) ----------------
        const int l = tid & 31;
        const int gsw = (l >> 2) & 1;      // SW32 input swizzle bit (lane-constant)
        const int ssw = l & 7;             // SW128 output swizzle (lane-constant)
        float* sout = smf + IN_F;

        float h0 = 0.f, h1 = 0.f, h2 = 0.f, h3 = 0.f;

        #pragma unroll 1
        for (int t = 0; t < NT; ++t) {
            const int s = t & 3, k = t >> 2;
            mbar_wait_acq(fullb + 8u * s, (uint32_t)(k & 1));

            const float* bx = smf + s * STAGE_F;           // X
            const float* bb = bx + SLOT_F;                 // B
            const float* b1 = bb + SLOT_F;                 // G1
            const float* b2 = b1 + SLOT_F;                 // G2
            const float* b3 = b2 + SLOT_F;                 // G3

            #pragma unroll
            for (int g = 0; g < 2; ++g) {
                const int gs = g ^ gsw;    // SW32: 16B halves swapped by row bit 2
                float4 xv[4], bv[4], a1[4], a2[4], a3[4];
                #pragma unroll
                for (int q = 0; q < 4; ++q) {
                    const int off = (l + 32 * q) * WT + 4 * gs;
                    xv[q] = *(const float4*)(bx + off);
                    bv[q] = *(const float4*)(bb + off);
                    a1[q] = *(const float4*)(b1 + off);
                    a2[q] = *(const float4*)(b2 + off);
                    a3[q] = *(const float4*)(b3 + off);
                }

                float ov[4][4];
                #pragma unroll
                for (int j = 0; j < 4; ++j) {
                    const float bx0 = COMP(bv[0], j) * COMP(xv[0], j);
                    const float bx1 = COMP(bv[1], j) * COMP(xv[1], j);
                    const float bx2 = COMP(bv[2], j) * COMP(xv[2], j);
                    const float bx3 = COMP(bv[3], j) * COMP(xv[3], j);

                    const float u0 = __shfl_sync(FULLM, (l == 31) ? 0.f : h0, (l + 31) & 31);
                    const float u1 = __shfl_sync(FULLM, (l == 31) ? h0  : h1, (l + 31) & 31);
                    const float u2 = __shfl_sync(FULLM, (l == 31) ? h1  : h2, (l + 31) & 31);
                    const float u3 = __shfl_sync(FULLM, (l == 31) ? h2  : h3, (l + 31) & 31);
                    const float d0 = __shfl_sync(FULLM, (l == 0) ? h1  : h0, (l + 1) & 31);
                    const float d1 = __shfl_sync(FULLM, (l == 0) ? h2  : h1, (l + 1) & 31);
                    const float d2 = __shfl_sync(FULLM, (l == 0) ? h3  : h2, (l + 1) & 31);
                    const float d3 = __shfl_sync(FULLM, (l == 0) ? 0.f : h3, (l + 1) & 31);

                    h0 = fmaf(COMP(a1[0], j), u0, fmaf(COMP(a2[0], j), h0, fmaf(COMP(a3[0], j), d0, bx0)));
                    h1 = fmaf(COMP(a1[1], j), u1, fmaf(COMP(a2[1], j), h1, fmaf(COMP(a3[1], j), d1, bx1)));
                    h2 = fmaf(COMP(a1[2], j), u2, fmaf(COMP(a2[2], j), h2, fmaf(COMP(a3[2], j), d2, bx2)));
                    h3 = fmaf(COMP(a1[3], j), u3, fmaf(COMP(a2[3], j), h3, fmaf(COMP(a3[3], j), d3, bx3)));

                    ov[0][j] = h0; ov[1][j] = h1; ov[2][j] = h2; ov[3][j] = h3;
                }

                // output batch store, SW128 swizzle: group G at 16B slot G^(row&7)
                const int G  = (t & 3) * 2 + g;
                const int sg = G ^ ssw;
                #pragma unroll
                for (int q = 0; q < 4; ++q) {
                    const int row = l + 32 * q;
                    float4 v;
                    v.x = ov[q][0]; v.y = ov[q][1]; v.z = ov[q][2]; v.w = ov[q][3];
                    *(float4*)(sout + row * 32 + 4 * sg) = v;
                }
            }

            __syncwarp();
            if (l == 0) mbar_arrive(emptyb + 8u * s);   // slot consumed

            if ((t & 3) == 3) {                          // flush 32-col batch via TMA store
                __syncwarp();
                if (l == 0) {
                    fence_async_shared();
                    tma_st2d(&mO, (t >> 2) * 32, cy, sb + (uint32_t)IN_F * 4u);
                    tma_st_commit();
                    tma_st_wait0();
                }
                __syncwarp();
            }
        }
    }
}

// ---------------- host ----------------
extern "C" void kernel_launch(void* const* d_in, const int* in_sizes, int n_in,
                              void* d_out, int out_size)
{
    typedef CUresult (*EncFn)(CUtensorMap*, CUtensorMapDataType, cuuint32_t, void*,
                              const cuuint64_t*, const cuuint64_t*, const cuuint32_t*,
                              const cuuint32_t*, CUtensorMapInterleave, CUtensorMapSwizzle,
                              CUtensorMapL2promotion, CUtensorMapFloatOOBfill);
    void* h = dlopen("libcuda.so.1", RTLD_NOW | RTLD_GLOBAL);
    if (!h) h = dlopen("libcuda.so", RTLD_NOW | RTLD_GLOBAL);
    EncFn enc = (EncFn)dlsym(h, "cuTensorMapEncodeTiled");

    const cuuint64_t gdim[2]    = {128, 512ull * 128};   // [w, plane*128+h]
    const cuuint64_t gstride[1] = {512};                 // 128 floats * 4B
    const cuuint32_t estr[2]    = {1, 1};
    const cuuint32_t box_in[2]  = {WT, 128};
    const cuuint32_t box_out[2] = {32, 128};

    CUtensorMap maps[5];
    for (int i = 0; i < 5; ++i) {
        enc(&maps[i], CU_TENSOR_MAP_DATA_TYPE_FLOAT32, 2, (void*)d_in[i],
            gdim, gstride, box_in, estr,
            CU_TENSOR_MAP_INTERLEAVE_NONE, CU_TENSOR_MAP_SWIZZLE_32B,
            CU_TENSOR_MAP_L2_PROMOTION_L2_128B, CU_TENSOR_MAP_FLOAT_OOB_FILL_NONE);
    }
    CUtensorMap mO;
    enc(&mO, CU_TENSOR_MAP_DATA_TYPE_FLOAT32, 2, d_out,
        gdim, gstride, box_out, estr,
        CU_TENSOR_MAP_INTERLEAVE_NONE, CU_TENSOR_MAP_SWIZZLE_128B,
        CU_TENSOR_MAP_L2_PROMOTION_L2_128B, CU_TENSOR_MAP_FLOAT_OOB_FILL_NONE);

    cudaFuncSetAttribute(gaterec2d_tma_kernel,
                         cudaFuncAttributeMaxDynamicSharedMemorySize, SMEM_BYTES);

    gaterec2d_tma_kernel<<<512, 64, SMEM_BYTES>>>(maps[0], maps[1], maps[2],
                                                  maps[3], maps[4], mO);
}

// round 7
// speedup vs baseline: 8.2086x; 1.0463x over previous
#include <cuda_runtime.h>
#include <cuda.h>
#include <dlfcn.h>
#include <cstdint>

// GateRecurrent2dnoind: H[h,w] = B*X + G1*H[h-1,w-1] + G2*H[h,w-1] + G3*H[h+1,w-1]
// [16, 32, 128, 128] fp32.
// 1 CTA = 1 plane, 64 threads. Thread 0: TMA producer (depth-2 mbarrier ring,
// 16-col stages x 5 tensors, SWIZZLE_64B). Warp 1: consumer shfl scan
// (lane l owns rows l,l+32,l+64,l+96). Output double-buffered (2 x 16 cols),
// flushed via TMA store with deferred wait_group — consumer never blocks on
// its own store. All bulk traffic bypasses the L1tex fill path.

#define HH      128
#define WT      16
#define NT      8
#define DEPTH   2
#define SLOT_F  (HH * WT)            // 2048 floats / tensor / stage
#define STAGE_F (5 * SLOT_F)         // 10240 floats = 40KB / stage
#define IN_F    (DEPTH * STAGE_F)    // 20480 floats
#define OUTBUF_F (HH * WT)           // 2048 floats per output buffer
#define SM_F    (IN_F + 2 * OUTBUF_F)
#define BAR_OFF (SM_F * 4)
#define SMEM_BYTES (BAR_OFF + 128)
#define STAGE_BYTES (STAGE_F * 4)    // 40960

#define FULLM 0xFFFFFFFFu
#define COMP(v, j) ((j) == 0 ? (v).x : (j) == 1 ? (v).y : (j) == 2 ? (v).z : (v).w)

// ---------------- PTX helpers ----------------
__device__ __forceinline__ void mbar_init(uint32_t a, uint32_t cnt) {
    asm volatile("mbarrier.init.shared.b64 [%0], %1;" :: "r"(a), "r"(cnt) : "memory");
}
__device__ __forceinline__ void mbar_expect_tx(uint32_t a, uint32_t bytes) {
    asm volatile("mbarrier.arrive.expect_tx.shared.b64 _, [%0], %1;"
                 :: "r"(a), "r"(bytes) : "memory");
}
__device__ __forceinline__ void mbar_arrive(uint32_t a) {
    asm volatile("mbarrier.arrive.shared.b64 _, [%0];" :: "r"(a) : "memory");
}
__device__ __forceinline__ void mbar_wait_acq(uint32_t a, uint32_t ph) {
    asm volatile(
        "{\n\t.reg .pred P;\n"
        "W%=:\n\t"
        "mbarrier.try_wait.parity.acquire.cta.shared::cta.b64 P, [%0], %1, 0x989680;\n\t"
        "@P bra D%=;\n\t"
        "bra W%=;\n"
        "D%=:\n\t}"
        :: "r"(a), "r"(ph) : "memory");
}
__device__ __forceinline__ void mbar_wait_rlx(uint32_t a, uint32_t ph) {
    asm volatile(
        "{\n\t.reg .pred P;\n"
        "W%=:\n\t"
        "mbarrier.try_wait.parity.relaxed.cta.shared::cta.b64 P, [%0], %1, 0x989680;\n\t"
        "@P bra D%=;\n\t"
        "bra W%=;\n"
        "D%=:\n\t}"
        :: "r"(a), "r"(ph) : "memory");
}
__device__ __forceinline__ void tma_ld2d(uint32_t smem, const void* map,
                                         int32_t cx, int32_t cy, uint32_t mbar) {
    asm volatile(
        "cp.async.bulk.tensor.2d.shared::cta.global.tile.mbarrier::complete_tx::bytes "
        "[%0], [%1, {%2, %3}], [%4];"
        :: "r"(smem), "l"(map), "r"(cx), "r"(cy), "r"(mbar) : "memory");
}
__device__ __forceinline__ void tma_st2d(const void* map, int32_t cx, int32_t cy,
                                         uint32_t smem) {
    asm volatile(
        "cp.async.bulk.tensor.2d.global.shared::cta.tile.bulk_group "
        "[%0, {%1, %2}], [%3];"
        :: "l"(map), "r"(cx), "r"(cy), "r"(smem) : "memory");
}
__device__ __forceinline__ void tma_st_commit() {
    asm volatile("cp.async.bulk.commit_group;" ::: "memory");
}
__device__ __forceinline__ void tma_st_wait1() {
    asm volatile("cp.async.bulk.wait_group 1;" ::: "memory");
}
__device__ __forceinline__ void tma_st_wait0() {
    asm volatile("cp.async.bulk.wait_group 0;" ::: "memory");
}
__device__ __forceinline__ void fence_async_shared() {
    asm volatile("fence.proxy.async.shared::cta;" ::: "memory");
}

// ---------------- kernel ----------------
__global__ __launch_bounds__(64)
void gaterec2d_tma16_kernel(const __grid_constant__ CUtensorMap mX,
                            const __grid_constant__ CUtensorMap mB,
                            const __grid_constant__ CUtensorMap m1,
                            const __grid_constant__ CUtensorMap m2,
                            const __grid_constant__ CUtensorMap m3,
                            const __grid_constant__ CUtensorMap mO)
{
    extern __shared__ float smf[];
    const uint32_t sb = (uint32_t)__cvta_generic_to_shared(smf);
    const int tid = threadIdx.x;
    const int cy  = blockIdx.x * HH;

    const uint32_t fullb  = sb + BAR_OFF;        // full[s]  at +8*s
    const uint32_t emptyb = sb + BAR_OFF + 16;   // empty[s] at +8*s

    if (tid == 0) {
        #pragma unroll
        for (int s = 0; s < DEPTH; ++s) {
            mbar_init(fullb  + 8u * s, 1);
            mbar_init(emptyb + 8u * s, 1);
        }
    }
    __syncthreads();

    if (tid == 0) {
        // ---------------- producer ----------------
        #pragma unroll 1
        for (int t = 0; t < NT; ++t) {
            const int s = t & 1, k = t >> 1;
            mbar_wait_rlx(emptyb + 8u * s, (uint32_t)((k & 1) ^ 1));
            mbar_expect_tx(fullb + 8u * s, STAGE_BYTES);
            const uint32_t slot = sb + (uint32_t)(s * STAGE_F) * 4u;
            const int cx = WT * t;
            tma_ld2d(slot + 0u * SLOT_F * 4u, &mX, cx, cy, fullb + 8u * s);
            tma_ld2d(slot + 1u * SLOT_F * 4u, &mB, cx, cy, fullb + 8u * s);
            tma_ld2d(slot + 2u * SLOT_F * 4u, &m1, cx, cy, fullb + 8u * s);
            tma_ld2d(slot + 3u * SLOT_F * 4u, &m2, cx, cy, fullb + 8u * s);
            tma_ld2d(slot + 4u * SLOT_F * 4u, &m3, cx, cy, fullb + 8u * s);
        }
    } else if (tid >= 32) {
        // ---------------- consumer (warp 1) ----------------
        const int l   = tid & 31;
        const int lsw = (l >> 1) & 3;    // SW64 swizzle term, lane-constant for owned rows

        float h0 = 0.f, h1 = 0.f, h2 = 0.f, h3 = 0.f;

        #pragma unroll 1
        for (int t = 0; t < NT; ++t) {
            const int s = t & 1, k = t >> 1;
            mbar_wait_acq(fullb + 8u * s, (uint32_t)(k & 1));

            // defer-wait: the TMA store issued 2 tiles ago must be done before
            // we overwrite output buffer (t&1). Allow 1 group outstanding.
            if (t >= 2) { if (l == 0) tma_st_wait1(); }
            __syncwarp();

            const float* bx = smf + s * STAGE_F;
            const float* bb = bx + SLOT_F;
            const float* b1 = bb + SLOT_F;
            const float* b2 = b1 + SLOT_F;
            const float* b3 = b2 + SLOT_F;
            float* sout = smf + IN_F + (t & 1) * OUTBUF_F;

            #pragma unroll
            for (int g = 0; g < 4; ++g) {
                const int gs = g ^ lsw;          // SW64: 16B slot within 64B row
                float4 xv[4], bv[4], a1[4], a2[4], a3[4];
                #pragma unroll
                for (int q = 0; q < 4; ++q) {
                    const int off = (l + 32 * q) * WT + 4 * gs;
                    xv[q] = *(const float4*)(bx + off);
                    bv[q] = *(const float4*)(bb + off);
                    a1[q] = *(const float4*)(b1 + off);
                    a2[q] = *(const float4*)(b2 + off);
                    a3[q] = *(const float4*)(b3 + off);
                }

                float ov[4][4];
                #pragma unroll
                for (int j = 0; j < 4; ++j) {
                    const float bx0 = COMP(bv[0], j) * COMP(xv[0], j);
                    const float bx1 = COMP(bv[1], j) * COMP(xv[1], j);
                    const float bx2 = COMP(bv[2], j) * COMP(xv[2], j);
                    const float bx3 = COMP(bv[3], j) * COMP(xv[3], j);

                    const float u0 = __shfl_sync(FULLM, (l == 31) ? 0.f : h0, (l + 31) & 31);
                    const float u1 = __shfl_sync(FULLM, (l == 31) ? h0  : h1, (l + 31) & 31);
                    const float u2 = __shfl_sync(FULLM, (l == 31) ? h1  : h2, (l + 31) & 31);
                    const float u3 = __shfl_sync(FULLM, (l == 31) ? h2  : h3, (l + 31) & 31);
                    const float d0 = __shfl_sync(FULLM, (l == 0) ? h1  : h0, (l + 1) & 31);
                    const float d1 = __shfl_sync(FULLM, (l == 0) ? h2  : h1, (l + 1) & 31);
                    const float d2 = __shfl_sync(FULLM, (l == 0) ? h3  : h2, (l + 1) & 31);
                    const float d3 = __shfl_sync(FULLM, (l == 0) ? 0.f : h3, (l + 1) & 31);

                    h0 = fmaf(COMP(a1[0], j), u0, fmaf(COMP(a2[0], j), h0, fmaf(COMP(a3[0], j), d0, bx0)));
                    h1 = fmaf(COMP(a1[1], j), u1, fmaf(COMP(a2[1], j), h1, fmaf(COMP(a3[1], j), d1, bx1)));
                    h2 = fmaf(COMP(a1[2], j), u2, fmaf(COMP(a2[2], j), h2, fmaf(COMP(a3[2], j), d2, bx2)));
                    h3 = fmaf(COMP(a1[3], j), u3, fmaf(COMP(a2[3], j), h3, fmaf(COMP(a3[3], j), d3, bx3)));

                    ov[0][j] = h0; ov[1][j] = h1; ov[2][j] = h2; ov[3][j] = h3;
                }

                #pragma unroll
                for (int q = 0; q < 4; ++q) {
                    const int row = l + 32 * q;
                    float4 v;
                    v.x = ov[q][0]; v.y = ov[q][1]; v.z = ov[q][2]; v.w = ov[q][3];
                    *(float4*)(sout + row * WT + 4 * gs) = v;
                }
            }

            __syncwarp();
            if (l == 0) {
                mbar_arrive(emptyb + 8u * s);                  // stage consumed
                fence_async_shared();
                tma_st2d(&mO, WT * t, cy,
                         sb + (uint32_t)(IN_F + (t & 1) * OUTBUF_F) * 4u);
                tma_st_commit();                               // no blocking wait here
            }
        }
        if (l == 0) tma_st_wait0();   // drain before SMEM teardown
    }
}

// ---------------- host ----------------
extern "C" void kernel_launch(void* const* d_in, const int* in_sizes, int n_in,
                              void* d_out, int out_size)
{
    typedef CUresult (*EncFn)(CUtensorMap*, CUtensorMapDataType, cuuint32_t, void*,
                              const cuuint64_t*, const cuuint64_t*, const cuuint32_t*,
                              const cuuint32_t*, CUtensorMapInterleave, CUtensorMapSwizzle,
                              CUtensorMapL2promotion, CUtensorMapFloatOOBfill);
    void* h = dlopen("libcuda.so.1", RTLD_NOW | RTLD_GLOBAL);
    if (!h) h = dlopen("libcuda.so", RTLD_NOW | RTLD_GLOBAL);
    EncFn enc = (EncFn)dlsym(h, "cuTensorMapEncodeTiled");

    const cuuint64_t gdim[2]    = {128, 512ull * 128};   // [w, plane*128 + h]
    const cuuint64_t gstride[1] = {512};                 // 128 floats * 4B
    const cuuint32_t estr[2]    = {1, 1};
    const cuuint32_t box[2]     = {WT, 128};             // 64B rows -> SW64

    CUtensorMap maps[5];
    for (int i = 0; i < 5; ++i) {
        enc(&maps[i], CU_TENSOR_MAP_DATA_TYPE_FLOAT32, 2, (void*)d_in[i],
            gdim, gstride, box, estr,
            CU_TENSOR_MAP_INTERLEAVE_NONE, CU_TENSOR_MAP_SWIZZLE_64B,
            CU_TENSOR_MAP_L2_PROMOTION_L2_128B, CU_TENSOR_MAP_FLOAT_OOB_FILL_NONE);
    }
    CUtensorMap mO;
    enc(&mO, CU_TENSOR_MAP_DATA_TYPE_FLOAT32, 2, d_out,
        gdim, gstride, box, estr,
        CU_TENSOR_MAP_INTERLEAVE_NONE, CU_TENSOR_MAP_SWIZZLE_64B,
        CU_TENSOR_MAP_L2_PROMOTION_L2_128B, CU_TENSOR_MAP_FLOAT_OOB_FILL_NONE);

    cudaFuncSetAttribute(gaterec2d_tma16_kernel,
                         cudaFuncAttributeMaxDynamicSharedMemorySize, SMEM_BYTES);

    gaterec2d_tma16_kernel<<<512, 64, SMEM_BYTES>>>(maps[0], maps[1], maps[2],
                                                    maps[3], maps[4], mO);
}